// round 3
// baseline (speedup 1.0000x reference)
#include <cuda_runtime.h>
#include <cstdint>

#define N_NODES 100000
#define N_FEAT  512
#define N_CLASS 64
#define N_EDGES 3200000

#define BM 128
#define BN 64
#define BK 32

// ---------------- scratch (static device globals; no allocation) ----------------
__device__ float g_h0[(size_t)N_NODES * N_CLASS];   // 25.6 MB
__device__ float g_h1[(size_t)N_NODES * N_CLASS];   // 25.6 MB
__device__ int   g_count[N_NODES];
__device__ int   g_row_start[N_NODES + 1];
__device__ int   g_cursor[N_NODES];
__device__ uint2 g_csr[N_EDGES];                    // (col, val_bits) 25.6 MB
__device__ int   g_block_sums[64];
__device__ int   g_block_offs[64];

// ---------------- CSR build ----------------
__global__ void zero_counts_kernel() {
    int i = blockIdx.x * blockDim.x + threadIdx.x;
    if (i < N_NODES) g_count[i] = 0;
}

__global__ void hist_kernel(const int* __restrict__ erow) {
    int e = blockIdx.x * blockDim.x + threadIdx.x;
    if (e < N_EDGES) atomicAdd(&g_count[erow[e]], 1);
}

// 25 blocks x 1024 threads x 4 items = 102400 >= N_NODES
__global__ void scan_pass1_kernel() {
    __shared__ int wsum[32];
    int t = threadIdx.x;
    int base = blockIdx.x * 4096;
    int s = 0;
#pragma unroll
    for (int i = 0; i < 4; i++) {
        int idx = base + t * 4 + i;
        if (idx < N_NODES) s += g_count[idx];
    }
#pragma unroll
    for (int o = 16; o; o >>= 1) s += __shfl_down_sync(0xffffffffu, s, o);
    if ((t & 31) == 0) wsum[t >> 5] = s;
    __syncthreads();
    if (t < 32) {
        int v = wsum[t];
#pragma unroll
        for (int o = 16; o; o >>= 1) v += __shfl_down_sync(0xffffffffu, v, o);
        if (t == 0) g_block_sums[blockIdx.x] = v;
    }
}

__global__ void scan_pass2_kernel(int nblk) {
    int t = threadIdx.x;  // 32 threads
    int v = (t < nblk) ? g_block_sums[t] : 0;
    int x = v;
#pragma unroll
    for (int o = 1; o < 32; o <<= 1) {
        int y = __shfl_up_sync(0xffffffffu, x, o);
        if (t >= o) x += y;
    }
    if (t < nblk) g_block_offs[t] = x - v;      // exclusive
    if (t == 31) g_row_start[N_NODES] = x;      // grand total
}

__global__ void scan_pass3_kernel() {
    __shared__ int woff[32];
    int t = threadIdx.x, lane = t & 31, wid = t >> 5;
    int base = blockIdx.x * 4096;
    int v[4];
    int s = 0;
#pragma unroll
    for (int i = 0; i < 4; i++) {
        int idx = base + t * 4 + i;
        v[i] = (idx < N_NODES) ? g_count[idx] : 0;
        s += v[i];
    }
    int x = s;
#pragma unroll
    for (int o = 1; o < 32; o <<= 1) {
        int y = __shfl_up_sync(0xffffffffu, x, o);
        if (lane >= o) x += y;
    }
    if (lane == 31) woff[wid] = x;
    __syncthreads();
    if (wid == 0) {
        int w = woff[lane];
        int xw = w;
#pragma unroll
        for (int o = 1; o < 32; o <<= 1) {
            int y = __shfl_up_sync(0xffffffffu, xw, o);
            if (lane >= o) xw += y;
        }
        woff[lane] = xw - w;  // exclusive warp offsets
    }
    __syncthreads();
    int off = g_block_offs[blockIdx.x] + woff[wid] + (x - s);
#pragma unroll
    for (int i = 0; i < 4; i++) {
        int idx = base + t * 4 + i;
        if (idx < N_NODES) {
            g_row_start[idx] = off;
            g_cursor[idx] = off;
        }
        off += v[i];
    }
}

__global__ void fill_kernel(const int* __restrict__ erow,
                            const int* __restrict__ ecol,
                            const float* __restrict__ eval) {
    int e = blockIdx.x * blockDim.x + threadIdx.x;
    if (e < N_EDGES) {
        int pos = atomicAdd(&g_cursor[erow[e]], 1);
        g_csr[pos] = make_uint2((unsigned)ecol[e], __float_as_uint(eval[e]));
    }
}

// ---------------- GEMM: g_h0 = X @ W  (fp32, f32x2 packed FMA) ----------------
__global__ void __launch_bounds__(256) gemm_kernel(const float* __restrict__ X,
                                                   const float* __restrict__ W) {
    __shared__ float As[BK][BM];  // k-major A tile
    __shared__ float Bs[BK][BN];

    int t = threadIdx.x;
    int block_row = blockIdx.x * BM;
    int tm = t >> 4;   // 0..15 -> 8 rows each
    int tn = t & 15;   // 0..15 -> 4 cols each

    unsigned long long acc[8][2];
#pragma unroll
    for (int i = 0; i < 8; i++) { acc[i][0] = 0ull; acc[i][1] = 0ull; }

    for (int k0 = 0; k0 < N_FEAT; k0 += BK) {
        // load A tile: 128 rows x 32 k, coalesced float4, transpose-store
#pragma unroll
        for (int i = 0; i < 4; i++) {
            int f4  = t + 256 * i;     // 0..1023
            int row = f4 >> 3;         // 0..127
            int c4  = f4 & 7;          // 0..7
            float4 vv = make_float4(0.f, 0.f, 0.f, 0.f);
            int gr = block_row + row;
            if (gr < N_NODES)
                vv = *(const float4*)(X + (size_t)gr * N_FEAT + k0 + c4 * 4);
            As[c4 * 4 + 0][row] = vv.x;
            As[c4 * 4 + 1][row] = vv.y;
            As[c4 * 4 + 2][row] = vv.z;
            As[c4 * 4 + 3][row] = vv.w;
        }
        // load B tile: 32 x 64
#pragma unroll
        for (int i = 0; i < 2; i++) {
            int f4 = t + 256 * i;      // 0..511
            int kr = f4 >> 4;          // 0..31
            int c4 = f4 & 15;          // 0..15
            *(float4*)&Bs[kr][c4 * 4] =
                *(const float4*)(W + (size_t)(k0 + kr) * N_CLASS + c4 * 4);
        }
        __syncthreads();

#pragma unroll
        for (int k = 0; k < BK; k++) {
            float4 a0 = *(const float4*)&As[k][tm * 8];
            float4 a1 = *(const float4*)&As[k][tm * 8 + 4];
            ulonglong2 b = *(const ulonglong2*)&Bs[k][tn * 4];
            float av[8] = {a0.x, a0.y, a0.z, a0.w, a1.x, a1.y, a1.z, a1.w};
#pragma unroll
            for (int i = 0; i < 8; i++) {
                unsigned ai = __float_as_uint(av[i]);
                unsigned long long a2;
                asm("mov.b64 %0, {%1, %2};" : "=l"(a2) : "r"(ai), "r"(ai));
                asm("fma.rn.f32x2 %0, %1, %2, %0;" : "+l"(acc[i][0]) : "l"(a2), "l"(b.x));
                asm("fma.rn.f32x2 %0, %1, %2, %0;" : "+l"(acc[i][1]) : "l"(a2), "l"(b.y));
            }
        }
        __syncthreads();
    }

#pragma unroll
    for (int i = 0; i < 8; i++) {
        int gr = block_row + tm * 8 + i;
        if (gr < N_NODES) {
            float2 lo = *(float2*)&acc[i][0];
            float2 hi = *(float2*)&acc[i][1];
            float4 o = make_float4(lo.x, lo.y, hi.x, hi.y);
            *(float4*)(g_h0 + (size_t)gr * N_CLASS + tn * 4) = o;
        }
    }
}

// ---------------- SpMM: warp per row, gather-only (no float atomics) ----------------
__global__ void __launch_bounds__(256) spmm_kernel(int src_is_h1) {
    const float2* __restrict__ hin = (const float2*)(src_is_h1 ? g_h1 : g_h0);
    float2* __restrict__ hout = (float2*)(src_is_h1 ? g_h0 : g_h1);

    int warp_global = (blockIdx.x * blockDim.x + threadIdx.x) >> 5;
    int lane = threadIdx.x & 31;
    if (warp_global >= N_NODES) return;
    int r = warp_global;

    int start = g_row_start[r];
    int end   = g_row_start[r + 1];

    float ax = 0.f, ay = 0.f;
    int e = start;
    while (e + 32 <= end) {
        uint2 p = g_csr[e + lane];
#pragma unroll
        for (int j = 0; j < 32; j++) {
            int   c = __shfl_sync(0xffffffffu, (int)p.x, j);
            float v = __shfl_sync(0xffffffffu, __uint_as_float(p.y), j);
            float2 g = __ldg(&hin[c * 32 + lane]);
            ax = fmaf(v, g.x, ax);
            ay = fmaf(v, g.y, ay);
        }
        e += 32;
    }
    int n = end - e;
    if (n > 0) {
        uint2 p = make_uint2(0u, 0u);
        if (lane < n) p = g_csr[e + lane];
        for (int j = 0; j < n; j++) {
            int   c = __shfl_sync(0xffffffffu, (int)p.x, j);
            float v = __shfl_sync(0xffffffffu, __uint_as_float(p.y), j);
            float2 g = __ldg(&hin[c * 32 + lane]);
            ax = fmaf(v, g.x, ax);
            ay = fmaf(v, g.y, ay);
        }
    }
    hout[r * 32 + lane] = make_float2(ax, ay);
}

// ---------------- bias + log_softmax ----------------
__global__ void __launch_bounds__(256) finalize_kernel(const float* __restrict__ bias,
                                                       float* __restrict__ out) {
    int warp_global = (blockIdx.x * blockDim.x + threadIdx.x) >> 5;
    int lane = threadIdx.x & 31;
    if (warp_global >= N_NODES) return;
    int r = warp_global;

    float2 v = ((const float2*)g_h0)[r * 32 + lane];
    float2 b = ((const float2*)bias)[lane];
    v.x += b.x;
    v.y += b.y;

    float m = fmaxf(v.x, v.y);
#pragma unroll
    for (int o = 16; o; o >>= 1) m = fmaxf(m, __shfl_xor_sync(0xffffffffu, m, o));
    float s = expf(v.x - m) + expf(v.y - m);
#pragma unroll
    for (int o = 16; o; o >>= 1) s += __shfl_xor_sync(0xffffffffu, s, o);
    float lg = m + logf(s);

    ((float2*)out)[r * 32 + lane] = make_float2(v.x - lg, v.y - lg);
}

// ---------------- launch ----------------
extern "C" void kernel_launch(void* const* d_in, const int* in_sizes, int n_in,
                              void* d_out, int out_size) {
    const float* x    = (const float*)d_in[0];
    const float* w    = (const float*)d_in[1];
    const float* bias = (const float*)d_in[2];
    const int*   erow = (const int*)d_in[3];
    const int*   ecol = (const int*)d_in[4];
    const float* eval = (const float*)d_in[5];
    // d_in[6] = nlayers (fixed at 2 by setup_inputs)

    // CSR build
    zero_counts_kernel<<<(N_NODES + 255) / 256, 256>>>();
    hist_kernel<<<(N_EDGES + 255) / 256, 256>>>(erow);
    scan_pass1_kernel<<<25, 1024>>>();
    scan_pass2_kernel<<<1, 32>>>(25);
    scan_pass3_kernel<<<25, 1024>>>();
    fill_kernel<<<(N_EDGES + 255) / 256, 256>>>(erow, ecol, eval);

    // h0 = X @ W
    gemm_kernel<<<(N_NODES + BM - 1) / BM, 256>>>(x, w);

    // two propagation layers (nlayers == 2)
    int warps_grid = (N_NODES * 32 + 255) / 256;  // 12500 blocks
    spmm_kernel<<<warps_grid, 256>>>(0);  // h0 -> h1
    spmm_kernel<<<warps_grid, 256>>>(1);  // h1 -> h0

    // bias + log_softmax -> d_out
    finalize_kernel<<<warps_grid, 256>>>(bias, (float*)d_out);
}